// round 2
// baseline (speedup 1.0000x reference)
#include <cuda_runtime.h>

#define NN        16384
#define INF       256
#define OUTF      128
#define GEMM_CTAS 256        // must be < guaranteed first-wave size (>=592)
#define RPC       8          // A-rows scanned per CTA
#define CAP       384        // per-row nnz cap (mean 32.8, sigma 5.7 -> 61 sigma)

// HW = H @ kernel^T (16384 x 128 fp32 = 8 MB, L2-resident)
__device__ float        g_HW[NN * OUTF];
__device__ unsigned int g_done = 0;   // gemm tiles completed
__device__ unsigned int g_fin  = 0;   // CTAs retired (for self-reset)

struct GemmSm { float hS[64][33]; float kS[32][OUTF + 4]; };   // 25.3 KB
struct AggSm  { int idx[RPC][CAP]; int cnt[RPC]; float red[OUTF]; }; // 12.8 KB
union  SmU    { GemmSm g; AggSm a; };

__global__ __launch_bounds__(256, 4) void gcn_fused(const float* __restrict__ A,
                                                    const float* __restrict__ H,
                                                    const float* __restrict__ W,
                                                    float* __restrict__ out) {
    __shared__ SmU sm;
    const int tid = threadIdx.x;
    const int bid = blockIdx.x;

    // ---------------- Phase 0 (first 256 CTAs): one 64x128 tile of HW ------
    if (bid < GEMM_CTAS) {
        const int tc   = tid & 31;          // cols [tc*4, tc*4+3]
        const int trg  = tid >> 5;          // rows [trg*8, trg*8+7]
        const int row0 = bid * 64;

        float acc[8][4];
#pragma unroll
        for (int r = 0; r < 8; r++)
#pragma unroll
            for (int c = 0; c < 4; c++) acc[r][c] = 0.f;

        for (int k0 = 0; k0 < INF; k0 += 32) {
#pragma unroll
            for (int p = 0; p < 8; p++) {
                int idx = p * 256 + tid;
                int r = idx >> 5, kk = idx & 31;
                sm.g.hS[r][kk] = H[(size_t)(row0 + r) * INF + k0 + kk];
            }
#pragma unroll
            for (int p = 0; p < 16; p++) {
                int idx = p * 256 + tid;
                int o = idx >> 5, kk = idx & 31;
                sm.g.kS[kk][o] = W[(size_t)o * INF + k0 + kk];
            }
            __syncthreads();
#pragma unroll
            for (int kk = 0; kk < 32; kk++) {
                float4 b = *(const float4*)&sm.g.kS[kk][tc * 4];
#pragma unroll
                for (int r = 0; r < 8; r++) {
                    float a = sm.g.hS[trg * 8 + r][kk];
                    acc[r][0] += a * b.x;
                    acc[r][1] += a * b.y;
                    acc[r][2] += a * b.z;
                    acc[r][3] += a * b.w;
                }
            }
            __syncthreads();
        }
#pragma unroll
        for (int r = 0; r < 8; r++) {
            float4 v = make_float4(acc[r][0], acc[r][1], acc[r][2], acc[r][3]);
            *(float4*)&g_HW[(size_t)(row0 + trg * 8 + r) * OUTF + tc * 4] = v;
        }
        __syncthreads();
        __threadfence();
        if (tid == 0) atomicAdd(&g_done, 1u);
    }
    __syncthreads();   // smem union handoff (gemm -> agg)

    // ---------------- Phase 1: scan RPC rows of A, collect nnz indices -----
    if (tid < RPC) sm.a.cnt[tid] = 0;
    __syncthreads();

    for (int r = 0; r < RPC; r++) {
        const size_t row = (size_t)bid * RPC + r;
        const float4* Arow = (const float4*)(A + row * NN);
#pragma unroll
        for (int it = 0; it < NN / (256 * 4); it++) {     // 16 iters
            int q = it * 256 + tid;                        // coalesced float4
            float4 v = __ldcs(&Arow[q]);                   // streaming hint
            int base = q * 4;
            if (v.x != 0.f) { int p = atomicAdd(&sm.a.cnt[r], 1); if (p < CAP) sm.a.idx[r][p] = base;     }
            if (v.y != 0.f) { int p = atomicAdd(&sm.a.cnt[r], 1); if (p < CAP) sm.a.idx[r][p] = base + 1; }
            if (v.z != 0.f) { int p = atomicAdd(&sm.a.cnt[r], 1); if (p < CAP) sm.a.idx[r][p] = base + 2; }
            if (v.w != 0.f) { int p = atomicAdd(&sm.a.cnt[r], 1); if (p < CAP) sm.a.idx[r][p] = base + 3; }
        }
    }
    __syncthreads();

    // ---------------- Phase 2: wait for HW, gather, normalize, write -------
    if (tid == 0) {
        while (atomicAdd(&g_done, 0u) < GEMM_CTAS) __nanosleep(64);
        __threadfence();
    }
    __syncthreads();

    const int c = tid & 127;     // output column
    const int h = tid >> 7;      // half: alternate neighbors
    for (int r = 0; r < RPC; r++) {
        const int cnt = sm.a.cnt[r];
        const int lim = cnt < CAP ? cnt : CAP;
        float acc = 0.f;
        for (int k = h; k < lim; k += 2)
            acc += g_HW[(size_t)sm.a.idx[r][k] * OUTF + c];   // L2-resident
        if (h) sm.a.red[c] = acc;
        __syncthreads();
        if (!h)
            out[((size_t)bid * RPC + r) * OUTF + c] = (acc + sm.a.red[c]) / (float)(cnt + 1);
        __syncthreads();
    }

    // ---------------- self-reset of flags by last-retiring CTA -------------
    if (tid == 0) {
        unsigned t = atomicAdd(&g_fin, 1u);
        if (t == gridDim.x - 1) {
            g_done = 0;
            g_fin  = 0;
            __threadfence();
        }
    }
}

extern "C" void kernel_launch(void* const* d_in, const int* in_sizes, int n_in,
                              void* d_out, int out_size) {
    const float* A = (const float*)d_in[0];   // [16384, 16384]
    const float* H = (const float*)d_in[1];   // [16384, 256]
    const float* W = (const float*)d_in[2];   // [128, 256]
    float* out = (float*)d_out;               // [16384, 128]
    (void)in_sizes; (void)n_in; (void)out_size;

    gcn_fused<<<NN / RPC, 256>>>(A, H, W, out);
}

// round 3
// speedup vs baseline: 1.0351x; 1.0351x over previous
#include <cuda_runtime.h>

#define NN        16384
#define INF       256
#define OUTF      128
#define GEMM_CTAS 512        // 32 HW rows per gemm CTA; < min first wave (592 @ occ4)
#define RPC       8          // A-rows scanned per CTA
#define CAP       256        // per-row nnz cap (mean 32.8, sigma 5.7)

// HW = H @ kernel^T (16384 x 128 fp32 = 8 MB, L2-resident)
__device__ float        g_HW[NN * OUTF];
__device__ unsigned int g_done = 0;   // gemm tiles completed
__device__ unsigned int g_fin  = 0;   // CTAs retired (for self-reset)

struct GemmSm { float hS[32][33]; float kS[32][OUTF + 4]; };          // 21.2 KB
struct AggSm  { int idx[RPC][CAP]; int cnt[RPC]; float red[OUTF]; };  // 8.7 KB
union  SmU    { GemmSm g; AggSm a; };

__global__ __launch_bounds__(256, 8) void gcn_fused(const float* __restrict__ A,
                                                    const float* __restrict__ H,
                                                    const float* __restrict__ W,
                                                    float* __restrict__ out) {
    __shared__ SmU sm;
    const int tid = threadIdx.x;
    const int bid = blockIdx.x;

    // -------- Phase 0 (first 512 CTAs): one 32x128 tile of HW = H @ W^T ----
    if (bid < GEMM_CTAS) {
        const int tc   = tid & 31;          // col group: cols [tc*4, tc*4+3]
        const int trg  = tid >> 5;          // row group: rows [trg*4, trg*4+3]
        const int row0 = bid * 32;

        float acc[4][4];
#pragma unroll
        for (int r = 0; r < 4; r++)
#pragma unroll
            for (int c = 0; c < 4; c++) acc[r][c] = 0.f;

        for (int k0 = 0; k0 < INF; k0 += 32) {
#pragma unroll
            for (int p = 0; p < 4; p++) {          // H tile 32x32
                int idx = p * 256 + tid;
                int r = idx >> 5, kk = idx & 31;
                sm.g.hS[r][kk] = H[(size_t)(row0 + r) * INF + k0 + kk];
            }
#pragma unroll
            for (int p = 0; p < 16; p++) {         // W tile 32k x 128o
                int idx = p * 256 + tid;
                int o = idx >> 5, kk = idx & 31;
                sm.g.kS[kk][o] = W[(size_t)o * INF + k0 + kk];
            }
            __syncthreads();
#pragma unroll
            for (int kk = 0; kk < 32; kk++) {
                float4 b = *(const float4*)&sm.g.kS[kk][tc * 4];
#pragma unroll
                for (int r = 0; r < 4; r++) {
                    float a = sm.g.hS[trg * 4 + r][kk];   // warp broadcast
                    acc[r][0] += a * b.x;
                    acc[r][1] += a * b.y;
                    acc[r][2] += a * b.z;
                    acc[r][3] += a * b.w;
                }
            }
            __syncthreads();
        }
#pragma unroll
        for (int r = 0; r < 4; r++) {
            float4 v = make_float4(acc[r][0], acc[r][1], acc[r][2], acc[r][3]);
            *(float4*)&g_HW[(size_t)(row0 + trg * 4 + r) * OUTF + tc * 4] = v;
        }
        __syncthreads();
        __threadfence();
        if (tid == 0) atomicAdd(&g_done, 1u);
    }
    __syncthreads();   // smem union handoff (gemm -> agg)

    // -------- Phase 1: scan RPC rows of A, collect nnz indices -------------
    if (tid < RPC) sm.a.cnt[tid] = 0;
    __syncthreads();

    for (int r = 0; r < RPC; r++) {
        const size_t row = (size_t)bid * RPC + r;
        const float4* Arow = (const float4*)(A + row * NN);
#pragma unroll
        for (int it = 0; it < NN / (256 * 4); it++) {     // 16 iters
            int q = it * 256 + tid;                        // coalesced float4
            float4 v = __ldcs(&Arow[q]);                   // streaming hint
            int base = q * 4;
            if (v.x != 0.f) { int p = atomicAdd(&sm.a.cnt[r], 1); if (p < CAP) sm.a.idx[r][p] = base;     }
            if (v.y != 0.f) { int p = atomicAdd(&sm.a.cnt[r], 1); if (p < CAP) sm.a.idx[r][p] = base + 1; }
            if (v.z != 0.f) { int p = atomicAdd(&sm.a.cnt[r], 1); if (p < CAP) sm.a.idx[r][p] = base + 2; }
            if (v.w != 0.f) { int p = atomicAdd(&sm.a.cnt[r], 1); if (p < CAP) sm.a.idx[r][p] = base + 3; }
        }
    }
    __syncthreads();

    // -------- Phase 2: wait for HW, gather, normalize, write ---------------
    if (tid == 0) {
        while (atomicAdd(&g_done, 0u) < GEMM_CTAS) __nanosleep(64);
        __threadfence();
    }
    __syncthreads();

    const int c = tid & 127;     // output column
    const int h = tid >> 7;      // half: alternate neighbors
    for (int r = 0; r < RPC; r++) {
        const int cnt = sm.a.cnt[r];
        const int lim = cnt < CAP ? cnt : CAP;
        float acc = 0.f;
        for (int k = h; k < lim; k += 2)
            acc += g_HW[(size_t)sm.a.idx[r][k] * OUTF + c];   // L2-resident
        if (h) sm.a.red[c] = acc;
        __syncthreads();
        if (!h)
            out[((size_t)bid * RPC + r) * OUTF + c] = (acc + sm.a.red[c]) / (float)(cnt + 1);
        __syncthreads();
    }

    // -------- self-reset of flags by last-retiring CTA ---------------------
    if (tid == 0) {
        unsigned t = atomicAdd(&g_fin, 1u);
        if (t == gridDim.x - 1) {
            g_done = 0;
            g_fin  = 0;
            __threadfence();
        }
    }
}

extern "C" void kernel_launch(void* const* d_in, const int* in_sizes, int n_in,
                              void* d_out, int out_size) {
    const float* A = (const float*)d_in[0];   // [16384, 16384]
    const float* H = (const float*)d_in[1];   // [16384, 256]
    const float* W = (const float*)d_in[2];   // [128, 256]
    float* out = (float*)d_out;               // [16384, 128]
    (void)in_sizes; (void)n_in; (void)out_size;

    gcn_fused<<<NN / RPC, 256>>>(A, H, W, out);
}